// round 10
// baseline (speedup 1.0000x reference)
#include <cuda_runtime.h>
#include <cuda_fp16.h>
#include <mma.h>
#include <math.h>
#include <stdint.h>

using namespace nvcuda;

#define T_STEPS 1024
#define BATCH   256
#define E_DIM   128

__device__ float g_xproj[134217728];

// ---------------------------------------------------------------------------
// helpers
// ---------------------------------------------------------------------------
__device__ __forceinline__ uint32_t smem_u32(const void* p) {
    uint32_t a;
    asm("{ .reg .u64 t; cvta.to.shared.u64 t, %1; cvt.u32.u64 %0, t; }" : "=r"(a) : "l"(p));
    return a;
}
__device__ __forceinline__ void cp16(uint32_t dst, const void* src) {
    asm volatile("cp.async.cg.shared.global [%0], [%1], 16;" :: "r"(dst), "l"(src));
}
__device__ __forceinline__ void cp_commit() { asm volatile("cp.async.commit_group;"); }
__device__ __forceinline__ void cp_wait1()  { asm volatile("cp.async.wait_group 1;"); }
__device__ __forceinline__ void cp_wait0()  { asm volatile("cp.async.wait_group 0;"); }

// ---------------------------------------------------------------------------
// Kernel 1: x_proj = x @ W_ih^T + bias. tf32 wmma (HW truncation, no RN pass),
// BM=128 BN=256 BK=32, warp tile 64x64, 2-stage cp.async pipeline.
// ---------------------------------------------------------------------------
#define GP2 36

__global__ __launch_bounds__(256, 1)
void xproj_gemm_v2(const float* __restrict__ A,
                   const float* __restrict__ W,
                   const float* __restrict__ bih,
                   const float* __restrict__ bhh)
{
    extern __shared__ float sm[];
    float* Asm   = sm;                                   // [2][128*36]
    float* Bsm   = sm + 2 * 128 * GP2;                   // [2][256*36]
    float* BiasT = sm + 2 * 128 * GP2 + 2 * 256 * GP2;   // [16*260]

    const int n0  = blockIdx.x * 256;
    const int m0  = blockIdx.y * 128;
    const int tid = threadIdx.x;
    const int warp = tid >> 5;
    const int wm = (warp >> 2) * 64;     // 0 or 64
    const int wn = (warp & 3) * 64;      // 0,64,128,192

    const uint32_t as_b = smem_u32(Asm);
    const uint32_t bs_b = smem_u32(Bsm);
    const int lrow = tid >> 3;
    const int lkq  = (tid & 7) * 4;

    for (int i = tid; i < 16 * 256; i += 256) {
        int r = i >> 8, c = i & 255;
        BiasT[r * 260 + c] = bih[n0 + c] + bhh[n0 + c];
    }
    __syncthreads();

    wmma::fragment<wmma::accumulator, 16, 16, 8, float> cf[4][4];
#pragma unroll
    for (int i = 0; i < 4; i++)
#pragma unroll
        for (int j = 0; j < 4; j++)
            wmma::load_matrix_sync(cf[i][j], &BiasT[wn + j * 16], 260, wmma::mem_row_major);

    auto issue = [&](int kt, int s) {
#pragma unroll
        for (int i = 0; i < 4; i++) {
            int row = lrow + i * 32;
            cp16(as_b + (uint32_t)(s * 128 * GP2 + row * GP2 + lkq) * 4,
                 &A[(size_t)(m0 + row) * 256 + kt * 32 + lkq]);
        }
#pragma unroll
        for (int i = 0; i < 8; i++) {
            int row = lrow + i * 32;
            cp16(bs_b + (uint32_t)(s * 256 * GP2 + row * GP2 + lkq) * 4,
                 &W[(size_t)(n0 + row) * 256 + kt * 32 + lkq]);
        }
        cp_commit();
    };

    issue(0, 0);
    for (int kt = 0; kt < 8; kt++) {
        int s = kt & 1;
        if (kt < 7) { issue(kt + 1, s ^ 1); cp_wait1(); }
        else        { cp_wait0(); }
        __syncthreads();
        const float* As = Asm + s * 128 * GP2;
        const float* Bs = Bsm + s * 256 * GP2;
#pragma unroll
        for (int kk = 0; kk < 32; kk += 8) {
            wmma::fragment<wmma::matrix_a, 16, 16, 8, wmma::precision::tf32, wmma::row_major> af[4];
            wmma::fragment<wmma::matrix_b, 16, 16, 8, wmma::precision::tf32, wmma::col_major> bf[4];
#pragma unroll
            for (int i = 0; i < 4; i++)
                wmma::load_matrix_sync(af[i], &As[(wm + i * 16) * GP2 + kk], GP2);
#pragma unroll
            for (int j = 0; j < 4; j++)
                wmma::load_matrix_sync(bf[j], &Bs[(wn + j * 16) * GP2 + kk], GP2);
#pragma unroll
            for (int i = 0; i < 4; i++)
#pragma unroll
                for (int j = 0; j < 4; j++)
                    wmma::mma_sync(cf[i][j], af[i], bf[j], cf[i][j]);
        }
        __syncthreads();
    }
#pragma unroll
    for (int i = 0; i < 4; i++)
#pragma unroll
        for (int j = 0; j < 4; j++)
            wmma::store_matrix_sync(
                &g_xproj[(size_t)(m0 + wm + i * 16) * 512 + n0 + wn + j * 16],
                cf[i][j], 512, wmma::mem_row_major);
}
#define GEMM_SMEM ((2 * 128 * GP2 + 2 * 256 * GP2 + 16 * 260) * 4)

// ---------------------------------------------------------------------------
// Recurrence: fp16 mma.sync, hi/lo h-split in n-dim, k-split across warp
// pairs. 64 CTAs x 4 batches, 512 threads (16 warps).
// Warp (kh, wl): k-half kh, gate rows {mt*128 + wl*16 + r}. Partials summed
// via smem psum; hi/lo combined by 2 uniform-slot shfl butterflies; epilogue
// exactly 1 item (e,b) per thread.
// ---------------------------------------------------------------------------
__device__ __forceinline__ void mma16816h(float* c, const uint32_t* a, uint32_t b0, uint32_t b1) {
    asm volatile(
        "mma.sync.aligned.m16n8k16.row.col.f32.f16.f16.f32 "
        "{%0,%1,%2,%3}, {%4,%5,%6,%7}, {%8,%9}, {%0,%1,%2,%3};"
        : "+f"(c[0]), "+f"(c[1]), "+f"(c[2]), "+f"(c[3])
        : "r"(a[0]), "r"(a[1]), "r"(a[2]), "r"(a[3]), "r"(b0), "r"(b1));
}
__device__ __forceinline__ uint32_t pkhf(float x, float y) {
    __half2 h = __floats2half2_rn(x, y);
    return *reinterpret_cast<uint32_t*>(&h);
}
__device__ __forceinline__ float sigm(float x)   { return __fdividef(1.f, 1.f + __expf(-x)); }
__device__ __forceinline__ float tanhf_(float x) { float e = __expf(2.f * x); return 1.f - __fdividef(2.f, e + 1.f); }

__device__ __forceinline__ void bt_write(char* bt, int e, int col, unsigned short v) {
    int kt = e >> 4, kk = e & 15;
    int half = kk >> 3, tq = (kk & 7) >> 1, lo2 = kk & 1;
    *reinterpret_cast<unsigned short*>(bt + kt * 256 + (col * 4 + tq) * 8 + half * 4 + lo2 * 2) = v;
}

__global__ __launch_bounds__(512, 1)
void lstm_rec_k2(const float* __restrict__ Whh,
                 const float* __restrict__ h0,
                 const float* __restrict__ c0,
                 float* __restrict__ out)
{
    __shared__ __align__(16) char Btile[2048];
    __shared__ __align__(16) float psum[2][8][4][32][4];   // 32 KB

    const int tid = threadIdx.x;
    const int w   = tid >> 5;
    const int l   = tid & 31;
    const int kh  = w >> 3;          // k-half
    const int wl  = w & 7;           // row-warp
    const int bg0 = blockIdx.x * 4;
    const int j   = l & 3;
    const int p   = j & 1;
    const int e   = wl * 16 + (l >> 2) + ((j < 2) ? 0 : 8);
    const int b   = 2 * p + kh;      // this thread's item batch

    // ---- W_hh fp16 A-fragments for this k-half: [mt][kt][4] ----
    uint32_t wf[4][4][4];
    {
        const int r0b = wl * 16 + (l >> 2);
        const int t2  = 2 * j;
#pragma unroll
        for (int mt = 0; mt < 4; mt++)
#pragma unroll
            for (int kt = 0; kt < 4; kt++) {
                int r0 = mt * 128 + r0b;
                int k0 = kh * 64 + kt * 16 + t2;
                const float* p00 = &Whh[(size_t)r0 * 128 + k0];
                const float* p10 = &Whh[(size_t)(r0 + 8) * 128 + k0];
                wf[mt][kt][0] = pkhf(p00[0], p00[1]);
                wf[mt][kt][1] = pkhf(p10[0], p10[1]);
                wf[mt][kt][2] = pkhf(p00[8], p00[9]);
                wf[mt][kt][3] = pkhf(p10[8], p10[9]);
            }
    }

    // ---- state + B-tile init: 1 item (e, b) per thread ----
    float creg;
    {
        float h = h0[(size_t)(bg0 + b) * 128 + e];
        creg = c0[(size_t)(bg0 + b) * 128 + e];
        __half hh = __float2half_rn(h);
        __half hl = __float2half_rn(h - __half2float(hh));
        bt_write(Btile, e, b,     __half_as_ushort(hh));
        bt_write(Btile, e, b + 4, __half_as_ushort(hl));
    }

    float xpc[4];
#pragma unroll
    for (int mt = 0; mt < 4; mt++)
        xpc[mt] = g_xproj[((size_t)bg0 + b) * 512 + mt * 128 + e];

    __syncthreads();

    for (int t = 0; t < T_STEPS; t++) {
        // prefetch next step xproj (hidden under MMA)
        float xpn[4];
        {
            int tn = (t + 1 < T_STEPS) ? t + 1 : t;
#pragma unroll
            for (int mt = 0; mt < 4; mt++)
                xpn[mt] = __ldg(&g_xproj[((size_t)tn * BATCH + bg0 + b) * 512 + mt * 128 + e]);
        }

        // ---- MMA sweep over this k-half: 16 MMAs, 4 chains ----
        float acc[4][4];
#pragma unroll
        for (int mt = 0; mt < 4; mt++)
#pragma unroll
            for (int c = 0; c < 4; c++) acc[mt][c] = 0.f;
#pragma unroll
        for (int kt = 0; kt < 4; kt++) {
            uint2 bv = *reinterpret_cast<const uint2*>(Btile + (kh * 4 + kt) * 256 + l * 8);
#pragma unroll
            for (int mt = 0; mt < 4; mt++)
                mma16816h(acc[mt], wf[mt][kt], bv.x, bv.y);
        }

        // ---- publish partials ----
#pragma unroll
        for (int mt = 0; mt < 4; mt++)
            *reinterpret_cast<float4*>(&psum[kh][wl][mt][l][0]) =
                make_float4(acc[mt][0], acc[mt][1], acc[mt][2], acc[mt][3]);
        __syncthreads();

        // ---- k-sum + hi/lo butterfly (slots kh and kh+2 are warp-uniform) ----
        float gate[4];
#pragma unroll
        for (int mt = 0; mt < 4; mt++) {
            float4 q = *reinterpret_cast<const float4*>(&psum[kh ^ 1][wl][mt][l][0]);
            float qA = (kh == 0) ? q.x : q.y;      // partner slot kh
            float qB = (kh == 0) ? q.z : q.w;      // partner slot kh+2
            float sA = acc[mt][kh]     + qA;       // rows rh=0 partial (n=2j+kh)
            float sB = acc[mt][kh + 2] + qB;       // rows rh=1 partial
            float fA = sA + __shfl_xor_sync(0xffffffffu, sA, 2);
            float fB = sB + __shfl_xor_sync(0xffffffffu, sB, 2);
            gate[mt] = (j < 2) ? fA : fB;
        }

        // ---- epilogue: 1 item per thread ----
        float gi = gate[0] + xpc[0];
        float gf = gate[1] + xpc[1];
        float gg = gate[2] + xpc[2];
        float go = gate[3] + xpc[3];
        float i_ = sigm(gi), f_ = sigm(gf), g_ = tanhf_(gg), o_ = sigm(go);
        creg = f_ * creg + i_ * g_;
        float h = o_ * tanhf_(creg);
        __half hh = __float2half_rn(h);
        __half hl = __float2half_rn(h - __half2float(hh));
        bt_write(Btile, e, b,     __half_as_ushort(hh));
        bt_write(Btile, e, b + 4, __half_as_ushort(hl));
        out[((size_t)t * BATCH + bg0 + b) * E_DIM + e] = __logf(1.f + __expf(h));

#pragma unroll
        for (int mt = 0; mt < 4; mt++) xpc[mt] = xpn[mt];
        __syncthreads();
    }
}

// ---------------------------------------------------------------------------
extern "C" void kernel_launch(void* const* d_in, const int* in_sizes, int n_in,
                              void* d_out, int out_size)
{
    const float* x   = (const float*)d_in[0];
    const float* h0  = (const float*)d_in[1];
    const float* c0  = (const float*)d_in[2];
    const float* Wih = (const float*)d_in[3];
    const float* Whh = (const float*)d_in[4];
    const float* bih = (const float*)d_in[5];
    const float* bhh = (const float*)d_in[6];
    float* out = (float*)d_out;

    cudaFuncSetAttribute((const void*)xproj_gemm_v2,
                         cudaFuncAttributeMaxDynamicSharedMemorySize, GEMM_SMEM);

    xproj_gemm_v2<<<dim3(2, 2048), 256, GEMM_SMEM>>>(x, Wih, bih, bhh);
    lstm_rec_k2<<<64, 512>>>(Whh, h0, c0, out);
}

// round 11
// speedup vs baseline: 1.2625x; 1.2625x over previous
#include <cuda_runtime.h>
#include <cuda_fp16.h>
#include <mma.h>
#include <math.h>
#include <stdint.h>

using namespace nvcuda;

#define T_STEPS 1024
#define BATCH   256
#define E_DIM   128

__device__ float g_xproj[134217728];

// ---------------------------------------------------------------------------
// helpers
// ---------------------------------------------------------------------------
__device__ __forceinline__ uint32_t smem_u32(const void* p) {
    uint32_t a;
    asm("{ .reg .u64 t; cvta.to.shared.u64 t, %1; cvt.u32.u64 %0, t; }" : "=r"(a) : "l"(p));
    return a;
}
__device__ __forceinline__ void cp16(uint32_t dst, const void* src) {
    asm volatile("cp.async.cg.shared.global [%0], [%1], 16;" :: "r"(dst), "l"(src));
}
__device__ __forceinline__ void cp_commit() { asm volatile("cp.async.commit_group;"); }
__device__ __forceinline__ void cp_wait1()  { asm volatile("cp.async.wait_group 1;"); }
__device__ __forceinline__ void cp_wait0()  { asm volatile("cp.async.wait_group 0;"); }

// ---------------------------------------------------------------------------
// Kernel 1: x_proj = x @ W_ih^T + bias. tf32 wmma, BM=128 BN=256 BK=32,
// warp tile 64x64, 2-stage cp.async pipeline. (validated R10: ~850us)
// ---------------------------------------------------------------------------
#define GP2 36

__global__ __launch_bounds__(256, 1)
void xproj_gemm_v2(const float* __restrict__ A,
                   const float* __restrict__ W,
                   const float* __restrict__ bih,
                   const float* __restrict__ bhh)
{
    extern __shared__ float sm[];
    float* Asm   = sm;
    float* Bsm   = sm + 2 * 128 * GP2;
    float* BiasT = sm + 2 * 128 * GP2 + 2 * 256 * GP2;

    const int n0  = blockIdx.x * 256;
    const int m0  = blockIdx.y * 128;
    const int tid = threadIdx.x;
    const int warp = tid >> 5;
    const int wm = (warp >> 2) * 64;
    const int wn = (warp & 3) * 64;

    const uint32_t as_b = smem_u32(Asm);
    const uint32_t bs_b = smem_u32(Bsm);
    const int lrow = tid >> 3;
    const int lkq  = (tid & 7) * 4;

    for (int i = tid; i < 16 * 256; i += 256) {
        int r = i >> 8, c = i & 255;
        BiasT[r * 260 + c] = bih[n0 + c] + bhh[n0 + c];
    }
    __syncthreads();

    wmma::fragment<wmma::accumulator, 16, 16, 8, float> cf[4][4];
#pragma unroll
    for (int i = 0; i < 4; i++)
#pragma unroll
        for (int j = 0; j < 4; j++)
            wmma::load_matrix_sync(cf[i][j], &BiasT[wn + j * 16], 260, wmma::mem_row_major);

    auto issue = [&](int kt, int s) {
#pragma unroll
        for (int i = 0; i < 4; i++) {
            int row = lrow + i * 32;
            cp16(as_b + (uint32_t)(s * 128 * GP2 + row * GP2 + lkq) * 4,
                 &A[(size_t)(m0 + row) * 256 + kt * 32 + lkq]);
        }
#pragma unroll
        for (int i = 0; i < 8; i++) {
            int row = lrow + i * 32;
            cp16(bs_b + (uint32_t)(s * 256 * GP2 + row * GP2 + lkq) * 4,
                 &W[(size_t)(n0 + row) * 256 + kt * 32 + lkq]);
        }
        cp_commit();
    };

    issue(0, 0);
    for (int kt = 0; kt < 8; kt++) {
        int s = kt & 1;
        if (kt < 7) { issue(kt + 1, s ^ 1); cp_wait1(); }
        else        { cp_wait0(); }
        __syncthreads();
        const float* As = Asm + s * 128 * GP2;
        const float* Bs = Bsm + s * 256 * GP2;
#pragma unroll
        for (int kk = 0; kk < 32; kk += 8) {
            wmma::fragment<wmma::matrix_a, 16, 16, 8, wmma::precision::tf32, wmma::row_major> af[4];
            wmma::fragment<wmma::matrix_b, 16, 16, 8, wmma::precision::tf32, wmma::col_major> bf[4];
#pragma unroll
            for (int i = 0; i < 4; i++)
                wmma::load_matrix_sync(af[i], &As[(wm + i * 16) * GP2 + kk], GP2);
#pragma unroll
            for (int j = 0; j < 4; j++)
                wmma::load_matrix_sync(bf[j], &Bs[(wn + j * 16) * GP2 + kk], GP2);
#pragma unroll
            for (int i = 0; i < 4; i++)
#pragma unroll
                for (int j = 0; j < 4; j++)
                    wmma::mma_sync(cf[i][j], af[i], bf[j], cf[i][j]);
        }
        __syncthreads();
    }
#pragma unroll
    for (int i = 0; i < 4; i++)
#pragma unroll
        for (int j = 0; j < 4; j++)
            wmma::store_matrix_sync(
                &g_xproj[(size_t)(m0 + wm + i * 16) * 512 + n0 + wn + j * 16],
                cf[i][j], 512, wmma::mem_row_major);
}
#define GEMM_SMEM ((2 * 128 * GP2 + 2 * 256 * GP2 + 16 * 260) * 4)

// ---------------------------------------------------------------------------
// Recurrence: R9 structure (fp16 mma.sync, hi/lo h in n-dim, register-
// stationary W, 64 CTAs x 4 batches, 256 threads) with:
//  - tanh.approx epilogue, - double-buffered B tile (1 bar/step),
//  - softplus+STG after the bar (overlaps next MMA phase).
// ---------------------------------------------------------------------------
__device__ __forceinline__ void mma16816h(float* c, const uint32_t* a, uint32_t b0, uint32_t b1) {
    asm volatile(
        "mma.sync.aligned.m16n8k16.row.col.f32.f16.f16.f32 "
        "{%0,%1,%2,%3}, {%4,%5,%6,%7}, {%8,%9}, {%0,%1,%2,%3};"
        : "+f"(c[0]), "+f"(c[1]), "+f"(c[2]), "+f"(c[3])
        : "r"(a[0]), "r"(a[1]), "r"(a[2]), "r"(a[3]), "r"(b0), "r"(b1));
}
__device__ __forceinline__ uint32_t pkhf(float x, float y) {
    __half2 h = __floats2half2_rn(x, y);
    return *reinterpret_cast<uint32_t*>(&h);
}
__device__ __forceinline__ float tanha(float x) {
    float r;
    asm("tanh.approx.f32 %0, %1;" : "=f"(r) : "f"(x));
    return r;
}
__device__ __forceinline__ float sigma_(float x) {
    return fmaf(0.5f, tanha(0.5f * x), 0.5f);
}

__device__ __forceinline__ void bt_write(char* bt, int e, int col, unsigned short v) {
    int kt = e >> 4, kk = e & 15;
    int half = kk >> 3, tq = (kk & 7) >> 1, lo2 = kk & 1;
    *reinterpret_cast<unsigned short*>(bt + kt * 256 + (col * 4 + tq) * 8 + half * 4 + lo2 * 2) = v;
}

__global__ __launch_bounds__(256, 1)
void lstm_rec_h5(const float* __restrict__ Whh,
                 const float* __restrict__ h0,
                 const float* __restrict__ c0,
                 float* __restrict__ out)
{
    __shared__ __align__(16) char Btile[2][2048];

    const int tid = threadIdx.x;
    const int w   = tid >> 5;
    const int l   = tid & 31;
    const int bg0 = blockIdx.x * 4;
    const int j   = l & 3;
    const int p   = j & 1;
    const int cb  = (j < 2) ? 0 : 2;
    const int e   = w * 16 + (l >> 2) + ((j < 2) ? 0 : 8);

    // ---- W_hh fp16 A-fragments (register-stationary) ----
    uint32_t wf[4][8][4];
    {
        const int r0b = w * 16 + (l >> 2);
        const int t2  = 2 * (l & 3);
#pragma unroll
        for (int mt = 0; mt < 4; mt++)
#pragma unroll
            for (int kt = 0; kt < 8; kt++) {
                int r0 = mt * 128 + r0b;
                int k0 = kt * 16 + t2;
                const float* p00 = &Whh[(size_t)r0 * 128 + k0];
                const float* p10 = &Whh[(size_t)(r0 + 8) * 128 + k0];
                wf[mt][kt][0] = pkhf(p00[0], p00[1]);
                wf[mt][kt][1] = pkhf(p10[0], p10[1]);
                wf[mt][kt][2] = pkhf(p00[8], p00[9]);
                wf[mt][kt][3] = pkhf(p10[8], p10[9]);
            }
    }

    // ---- state + B-tile[0] init: 2 items per thread ----
    float creg[2];
#pragma unroll
    for (int i = 0; i < 2; i++) {
        int b = 2 * p + i;
        float h = h0[(size_t)(bg0 + b) * 128 + e];
        creg[i] = c0[(size_t)(bg0 + b) * 128 + e];
        __half hh = __float2half_rn(h);
        __half hl = __float2half_rn(h - __half2float(hh));
        bt_write(Btile[0], e, b,     __half_as_ushort(hh));
        bt_write(Btile[0], e, b + 4, __half_as_ushort(hl));
    }

    float xpc[4][2];
#pragma unroll
    for (int mt = 0; mt < 4; mt++)
#pragma unroll
        for (int i = 0; i < 2; i++)
            xpc[mt][i] = g_xproj[((size_t)bg0 + 2 * p + i) * 512 + mt * 128 + e];

    float hprev[2] = {0.f, 0.f};   // h of step t-1, softplus'd after the bar
    __syncthreads();

    for (int t = 0; t < T_STEPS; t++) {
        const char* bt_rd = Btile[t & 1];
        char* bt_wr = Btile[(t + 1) & 1];

        // prefetch next step xproj (hidden under MMA)
        float xpn[4][2];
        {
            int tn = (t + 1 < T_STEPS) ? t + 1 : t;
#pragma unroll
            for (int mt = 0; mt < 4; mt++)
#pragma unroll
                for (int i = 0; i < 2; i++)
                    xpn[mt][i] = __ldg(&g_xproj[((size_t)tn * BATCH + bg0 + 2 * p + i) * 512
                                                + mt * 128 + e]);
        }

        // ---- deferred softplus + STG for step t-1 (overlaps this MMA) ----
        if (t > 0) {
#pragma unroll
            for (int i = 0; i < 2; i++) {
                int b = 2 * p + i;
                out[((size_t)(t - 1) * BATCH + bg0 + b) * E_DIM + e] =
                    __logf(1.f + __expf(hprev[i]));
            }
        }

        // ---- one MMA sweep (reads bt_rd only) ----
        float acc[4][4];
#pragma unroll
        for (int mt = 0; mt < 4; mt++)
#pragma unroll
            for (int c = 0; c < 4; c++) acc[mt][c] = 0.f;
#pragma unroll
        for (int kt = 0; kt < 8; kt++) {
            uint2 bv = *reinterpret_cast<const uint2*>(bt_rd + kt * 256 + l * 8);
#pragma unroll
            for (int mt = 0; mt < 4; mt++)
                mma16816h(acc[mt], wf[mt][kt], bv.x, bv.y);
        }

        // ---- hi/lo butterfly (intra-warp only) ----
#pragma unroll
        for (int mt = 0; mt < 4; mt++)
#pragma unroll
            for (int c = 0; c < 4; c++)
                acc[mt][c] += __shfl_xor_sync(0xffffffffu, acc[mt][c], 2);

        // ---- epilogue: 2 items; write h into bt_wr (other buffer) ----
#pragma unroll
        for (int i = 0; i < 2; i++) {
            int c = cb + i;
            int b = 2 * p + i;
            float gi = acc[0][c] + xpc[0][i];
            float gf = acc[1][c] + xpc[1][i];
            float gg = acc[2][c] + xpc[2][i];
            float go = acc[3][c] + xpc[3][i];
            float i_ = sigma_(gi), f_ = sigma_(gf), o_ = sigma_(go);
            float g_ = tanha(gg);
            creg[i] = f_ * creg[i] + i_ * g_;
            float h = o_ * tanha(creg[i]);
            __half hh = __float2half_rn(h);
            __half hl = __float2half_rn(h - __half2float(hh));
            bt_write(bt_wr, e, b,     __half_as_ushort(hh));
            bt_write(bt_wr, e, b + 4, __half_as_ushort(hl));
            hprev[i] = h;
        }
#pragma unroll
        for (int mt = 0; mt < 4; mt++)
#pragma unroll
            for (int i = 0; i < 2; i++) xpc[mt][i] = xpn[mt][i];

        __syncthreads();   // the ONLY bar: bt_wr complete before next MMA reads it
    }

    // final step's output
#pragma unroll
    for (int i = 0; i < 2; i++) {
        int b = 2 * p + i;
        out[((size_t)(T_STEPS - 1) * BATCH + bg0 + b) * E_DIM + e] =
            __logf(1.f + __expf(hprev[i]));
    }
}

// ---------------------------------------------------------------------------
extern "C" void kernel_launch(void* const* d_in, const int* in_sizes, int n_in,
                              void* d_out, int out_size)
{
    const float* x   = (const float*)d_in[0];
    const float* h0  = (const float*)d_in[1];
    const float* c0  = (const float*)d_in[2];
    const float* Wih = (const float*)d_in[3];
    const float* Whh = (const float*)d_in[4];
    const float* bih = (const float*)d_in[5];
    const float* bhh = (const float*)d_in[6];
    float* out = (float*)d_out;

    cudaFuncSetAttribute((const void*)xproj_gemm_v2,
                         cudaFuncAttributeMaxDynamicSharedMemorySize, GEMM_SMEM);

    xproj_gemm_v2<<<dim3(2, 2048), 256, GEMM_SMEM>>>(x, Wih, bih, bhh);
    lstm_rec_h5<<<64, 256>>>(Whh, h0, c0, out);
}

// round 12
// speedup vs baseline: 1.4211x; 1.1257x over previous
#include <cuda_runtime.h>
#include <cuda_fp16.h>
#include <mma.h>
#include <math.h>
#include <stdint.h>

using namespace nvcuda;

#define T_STEPS 1024
#define BATCH   256
#define E_DIM   128

__device__ float g_xproj[134217728];

// ---------------------------------------------------------------------------
// helpers
// ---------------------------------------------------------------------------
__device__ __forceinline__ uint32_t smem_u32(const void* p) {
    uint32_t a;
    asm("{ .reg .u64 t; cvta.to.shared.u64 t, %1; cvt.u32.u64 %0, t; }" : "=r"(a) : "l"(p));
    return a;
}
__device__ __forceinline__ void cp16(uint32_t dst, const void* src) {
    asm volatile("cp.async.cg.shared.global [%0], [%1], 16;" :: "r"(dst), "l"(src));
}
__device__ __forceinline__ void cp_commit() { asm volatile("cp.async.commit_group;"); }
__device__ __forceinline__ void cp_wait2()  { asm volatile("cp.async.wait_group 2;"); }

// ---------------------------------------------------------------------------
// Kernel 1: x_proj = x @ W_ih^T + bias. tf32 wmma, BM=128 BN=256 BK=32,
// warp tile 64x64, 3-stage cp.async pipeline.
// ---------------------------------------------------------------------------
#define GP2 36

__global__ __launch_bounds__(256, 1)
void xproj_gemm_v3(const float* __restrict__ A,
                   const float* __restrict__ W,
                   const float* __restrict__ bih,
                   const float* __restrict__ bhh)
{
    extern __shared__ float sm[];
    float* Asm   = sm;                                     // [3][128*GP2]
    float* Bsm   = sm + 3 * 128 * GP2;                     // [3][256*GP2]
    float* BiasT = sm + 3 * 128 * GP2 + 3 * 256 * GP2;     // [16*260]

    const int n0  = blockIdx.x * 256;
    const int m0  = blockIdx.y * 128;
    const int tid = threadIdx.x;
    const int warp = tid >> 5;
    const int wm = (warp >> 2) * 64;
    const int wn = (warp & 3) * 64;

    const uint32_t as_b = smem_u32(Asm);
    const uint32_t bs_b = smem_u32(Bsm);
    const int lrow = tid >> 3;
    const int lkq  = (tid & 7) * 4;

    for (int i = tid; i < 16 * 256; i += 256) {
        int r = i >> 8, c = i & 255;
        BiasT[r * 260 + c] = bih[n0 + c] + bhh[n0 + c];
    }
    __syncthreads();

    wmma::fragment<wmma::accumulator, 16, 16, 8, float> cf[4][4];
#pragma unroll
    for (int i = 0; i < 4; i++)
#pragma unroll
        for (int j = 0; j < 4; j++)
            wmma::load_matrix_sync(cf[i][j], &BiasT[wn + j * 16], 260, wmma::mem_row_major);

    auto issue = [&](int kt, int s) {
#pragma unroll
        for (int i = 0; i < 4; i++) {
            int row = lrow + i * 32;
            cp16(as_b + (uint32_t)(s * 128 * GP2 + row * GP2 + lkq) * 4,
                 &A[(size_t)(m0 + row) * 256 + kt * 32 + lkq]);
        }
#pragma unroll
        for (int i = 0; i < 8; i++) {
            int row = lrow + i * 32;
            cp16(bs_b + (uint32_t)(s * 256 * GP2 + row * GP2 + lkq) * 4,
                 &W[(size_t)(n0 + row) * 256 + kt * 32 + lkq]);
        }
        cp_commit();
    };

    issue(0, 0);
    issue(1, 1);
    for (int kt = 0; kt < 8; kt++) {
        int s = kt % 3;
        if (kt + 2 < 8) issue(kt + 2, (kt + 2) % 3);
        else            cp_commit();                 // empty group keeps accounting
        cp_wait2();                                  // groups <= kt complete
        __syncthreads();
        const float* As = Asm + s * 128 * GP2;
        const float* Bs = Bsm + s * 256 * GP2;
#pragma unroll
        for (int kk = 0; kk < 32; kk += 8) {
            wmma::fragment<wmma::matrix_a, 16, 16, 8, wmma::precision::tf32, wmma::row_major> af[4];
            wmma::fragment<wmma::matrix_b, 16, 16, 8, wmma::precision::tf32, wmma::col_major> bf[4];
#pragma unroll
            for (int i = 0; i < 4; i++)
                wmma::load_matrix_sync(af[i], &As[(wm + i * 16) * GP2 + kk], GP2);
#pragma unroll
            for (int j = 0; j < 4; j++)
                wmma::load_matrix_sync(bf[j], &Bs[(wn + j * 16) * GP2 + kk], GP2);
#pragma unroll
            for (int i = 0; i < 4; i++)
#pragma unroll
                for (int j = 0; j < 4; j++)
                    wmma::mma_sync(cf[i][j], af[i], bf[j], cf[i][j]);
        }
        __syncthreads();
    }
#pragma unroll
    for (int i = 0; i < 4; i++)
#pragma unroll
        for (int j = 0; j < 4; j++)
            wmma::store_matrix_sync(
                &g_xproj[(size_t)(m0 + wm + i * 16) * 512 + n0 + wn + j * 16],
                cf[i][j], 512, wmma::mem_row_major);
}
#define GEMM3_SMEM ((3 * 128 * GP2 + 3 * 256 * GP2 + 16 * 260) * 4)

// ---------------------------------------------------------------------------
// Recurrence: R11 structure + cp.async xproj ring (3 steps deep, zero xp
// registers, still ONE bar/step) + split MMA chains (2x depth-4 per mt).
// ---------------------------------------------------------------------------
__device__ __forceinline__ void mma16816h(float* c, const uint32_t* a, uint32_t b0, uint32_t b1) {
    asm volatile(
        "mma.sync.aligned.m16n8k16.row.col.f32.f16.f16.f32 "
        "{%0,%1,%2,%3}, {%4,%5,%6,%7}, {%8,%9}, {%0,%1,%2,%3};"
        : "+f"(c[0]), "+f"(c[1]), "+f"(c[2]), "+f"(c[3])
        : "r"(a[0]), "r"(a[1]), "r"(a[2]), "r"(a[3]), "r"(b0), "r"(b1));
}
__device__ __forceinline__ uint32_t pkhf(float x, float y) {
    __half2 h = __floats2half2_rn(x, y);
    return *reinterpret_cast<uint32_t*>(&h);
}
__device__ __forceinline__ float tanha(float x) {
    float r;
    asm("tanh.approx.f32 %0, %1;" : "=f"(r) : "f"(x));
    return r;
}
__device__ __forceinline__ float sigma_(float x) {
    return fmaf(0.5f, tanha(0.5f * x), 0.5f);
}
__device__ __forceinline__ void bt_write(char* bt, int e, int col, unsigned short v) {
    int kt = e >> 4, kk = e & 15;
    int half = kk >> 3, tq = (kk & 7) >> 1, lo2 = kk & 1;
    *reinterpret_cast<unsigned short*>(bt + kt * 256 + (col * 4 + tq) * 8 + half * 4 + lo2 * 2) = v;
}

__global__ __launch_bounds__(256, 1)
void lstm_rec_h6(const float* __restrict__ Whh,
                 const float* __restrict__ h0,
                 const float* __restrict__ c0,
                 float* __restrict__ out)
{
    __shared__ __align__(16) char  Btile[2][2048];
    __shared__ __align__(16) float xring[4][2048];   // 4-stage xp ring, 32 KB

    const int tid = threadIdx.x;
    const int w   = tid >> 5;
    const int l   = tid & 31;
    const int bg0 = blockIdx.x * 4;
    const int j   = l & 3;
    const int p   = j & 1;
    const int cb  = (j < 2) ? 0 : 2;
    const int e   = w * 16 + (l >> 2) + ((j < 2) ? 0 : 8);

    // ---- W_hh fp16 A-fragments (register-stationary) ----
    uint32_t wf[4][8][4];
    {
        const int r0b = w * 16 + (l >> 2);
        const int t2  = 2 * (l & 3);
#pragma unroll
        for (int mt = 0; mt < 4; mt++)
#pragma unroll
            for (int kt = 0; kt < 8; kt++) {
                int r0 = mt * 128 + r0b;
                int k0 = kt * 16 + t2;
                const float* p00 = &Whh[(size_t)r0 * 128 + k0];
                const float* p10 = &Whh[(size_t)(r0 + 8) * 128 + k0];
                wf[mt][kt][0] = pkhf(p00[0], p00[1]);
                wf[mt][kt][1] = pkhf(p10[0], p10[1]);
                wf[mt][kt][2] = pkhf(p00[8], p00[9]);
                wf[mt][kt][3] = pkhf(p10[8], p10[9]);
            }
    }

    // ---- state + B-tile[0] init ----
    float creg[2];
#pragma unroll
    for (int i = 0; i < 2; i++) {
        int b = 2 * p + i;
        float h = h0[(size_t)(bg0 + b) * 128 + e];
        creg[i] = c0[(size_t)(bg0 + b) * 128 + e];
        __half hh = __float2half_rn(h);
        __half hl = __float2half_rn(h - __half2float(hh));
        bt_write(Btile[0], e, b,     __half_as_ushort(hh));
        bt_write(Btile[0], e, b + 4, __half_as_ushort(hl));
    }

    // ---- xp ring: thread tid copies 8 contiguous floats of each stage ----
    const uint32_t xr_b = smem_u32(xring);
    auto xissue = [&](int t) {
        if (t < T_STEPS) {
            const float* src = &g_xproj[((size_t)t * BATCH + bg0 + (tid >> 6)) * 512
                                        + (tid & 63) * 8];
            uint32_t dst = xr_b + (uint32_t)((t & 3) * 8192 + tid * 32);
            cp16(dst, src);
            cp16(dst + 16, src + 4);
        }
        cp_commit();
    };
    xissue(0); xissue(1); xissue(2);
    cp_wait2();            // stage 0 resident
    float hprev[2] = {0.f, 0.f};
    __syncthreads();

    for (int t = 0; t < T_STEPS; t++) {
        const char* bt_rd = Btile[t & 1];
        char* bt_wr = Btile[(t + 1) & 1];

        // deferred softplus + STG for step t-1 (overlaps this step's MMA)
        if (t > 0) {
#pragma unroll
            for (int i = 0; i < 2; i++) {
                int b = 2 * p + i;
                out[((size_t)(t - 1) * BATCH + bg0 + b) * E_DIM + e] =
                    __logf(1.f + __expf(hprev[i]));
            }
        }

        // ---- MMA sweep: two depth-4 chains per mt ----
        float accA[4][4], accB[4][4];
#pragma unroll
        for (int mt = 0; mt < 4; mt++)
#pragma unroll
            for (int c = 0; c < 4; c++) { accA[mt][c] = 0.f; accB[mt][c] = 0.f; }
#pragma unroll
        for (int kt = 0; kt < 8; kt++) {
            uint2 bv = *reinterpret_cast<const uint2*>(bt_rd + kt * 256 + l * 8);
#pragma unroll
            for (int mt = 0; mt < 4; mt++)
                mma16816h((kt < 4) ? accA[mt] : accB[mt], wf[mt][kt], bv.x, bv.y);
        }

        // ---- combine + hi/lo butterfly ----
        float acc[4][4];
#pragma unroll
        for (int mt = 0; mt < 4; mt++)
#pragma unroll
            for (int c = 0; c < 4; c++) {
                float v = accA[mt][c] + accB[mt][c];
                acc[mt][c] = v + __shfl_xor_sync(0xffffffffu, v, 2);
            }

        // ---- epilogue: xp from smem ring (stage t), 2 items ----
        const float* xs = xring[t & 3];
#pragma unroll
        for (int i = 0; i < 2; i++) {
            int c = cb + i;
            int b = 2 * p + i;
            const float* xrow = xs + b * 512 + e;
            float gi = acc[0][c] + xrow[0];
            float gf = acc[1][c] + xrow[128];
            float gg = acc[2][c] + xrow[256];
            float go = acc[3][c] + xrow[384];
            float i_ = sigma_(gi), f_ = sigma_(gf), o_ = sigma_(go);
            float g_ = tanha(gg);
            creg[i] = f_ * creg[i] + i_ * g_;
            float h = o_ * tanha(creg[i]);
            __half hh = __float2half_rn(h);
            __half hl = __float2half_rn(h - __half2float(hh));
            bt_write(bt_wr, e, b,     __half_as_ushort(hh));
            bt_write(bt_wr, e, b + 4, __half_as_ushort(hl));
            hprev[i] = h;
        }

        xissue(t + 3);     // refill ring 3 steps ahead
        cp_wait2();        // stage t+1 resident
        __syncthreads();   // single bar: B-tile handoff + ring visibility
    }

    // final step's output
#pragma unroll
    for (int i = 0; i < 2; i++) {
        int b = 2 * p + i;
        out[((size_t)(T_STEPS - 1) * BATCH + bg0 + b) * E_DIM + e] =
            __logf(1.f + __expf(hprev[i]));
    }
}

// ---------------------------------------------------------------------------
extern "C" void kernel_launch(void* const* d_in, const int* in_sizes, int n_in,
                              void* d_out, int out_size)
{
    const float* x   = (const float*)d_in[0];
    const float* h0  = (const float*)d_in[1];
    const float* c0  = (const float*)d_in[2];
    const float* Wih = (const float*)d_in[3];
    const float* Whh = (const float*)d_in[4];
    const float* bih = (const float*)d_in[5];
    const float* bhh = (const float*)d_in[6];
    float* out = (float*)d_out;

    cudaFuncSetAttribute((const void*)xproj_gemm_v3,
                         cudaFuncAttributeMaxDynamicSharedMemorySize, GEMM3_SMEM);

    xproj_gemm_v3<<<dim3(2, 2048), 256, GEMM3_SMEM>>>(x, Wih, bih, bhh);
    lstm_rec_h6<<<64, 256>>>(Whh, h0, c0, out);
}

// round 15
// speedup vs baseline: 2.0207x; 1.4219x over previous
#include <cuda_runtime.h>
#include <cuda_fp16.h>
#include <mma.h>
#include <math.h>
#include <stdint.h>

using namespace nvcuda;

#define T_STEPS 1024
#define BATCH   256
#define E_DIM   128

__device__ float  g_xproj[134217728];   // x_proj fp32 [M][512]
__device__ __half g_xh16[67108864];     // x fp16 [M=262144][256]
__device__ __half g_wh[131072];         // W_ih fp16 [512][256]

// ---------------------------------------------------------------------------
// helpers
// ---------------------------------------------------------------------------
__device__ __forceinline__ uint32_t smem_u32(const void* p) {
    uint32_t a;
    asm("{ .reg .u64 t; cvta.to.shared.u64 t, %1; cvt.u32.u64 %0, t; }" : "=r"(a) : "l"(p));
    return a;
}
__device__ __forceinline__ void cp16(uint32_t dst, const void* src) {
    asm volatile("cp.async.cg.shared.global [%0], [%1], 16;" :: "r"(dst), "l"(src));
}
__device__ __forceinline__ void cp_commit() { asm volatile("cp.async.commit_group;"); }
__device__ __forceinline__ void cp_wait0()  { asm volatile("cp.async.wait_group 0;"); }
__device__ __forceinline__ void cp_wait1()  { asm volatile("cp.async.wait_group 1;"); }
__device__ __forceinline__ void cp_wait2()  { asm volatile("cp.async.wait_group 2;"); }
__device__ __forceinline__ void mma16816h(float* c, const uint32_t* a, uint32_t b0, uint32_t b1) {
    asm volatile(
        "mma.sync.aligned.m16n8k16.row.col.f32.f16.f16.f32 "
        "{%0,%1,%2,%3}, {%4,%5,%6,%7}, {%8,%9}, {%0,%1,%2,%3};"
        : "+f"(c[0]), "+f"(c[1]), "+f"(c[2]), "+f"(c[3])
        : "r"(a[0]), "r"(a[1]), "r"(a[2]), "r"(a[3]), "r"(b0), "r"(b1));
}
__device__ __forceinline__ uint32_t pkhf(float x, float y) {
    __half2 h = __floats2half2_rn(x, y);
    return *reinterpret_cast<uint32_t*>(&h);
}
__device__ __forceinline__ float tanha(float x) {
    float r;
    asm("tanh.approx.f32 %0, %1;" : "=f"(r) : "f"(x));
    return r;
}
__device__ __forceinline__ float sigma_(float x) {
    return fmaf(0.5f, tanha(0.5f * x), 0.5f);
}

// ---------------------------------------------------------------------------
// Prep: x -> fp16, W_ih -> fp16
// ---------------------------------------------------------------------------
__global__ void prep_x16(const float* __restrict__ x) {
    const int stride = gridDim.x * blockDim.x;
    for (int u = blockIdx.x * blockDim.x + threadIdx.x; u < 16777216; u += stride) {
        float4 v = reinterpret_cast<const float4*>(x)[u];
        uint2 ph;
        ph.x = ((uint32_t)__half_as_ushort(__float2half_rn(v.y)) << 16) |
               __half_as_ushort(__float2half_rn(v.x));
        ph.y = ((uint32_t)__half_as_ushort(__float2half_rn(v.w)) << 16) |
               __half_as_ushort(__float2half_rn(v.z));
        reinterpret_cast<uint2*>(g_xh16)[u] = ph;
    }
}
__global__ void prep_w(const float* __restrict__ W) {
    int u = blockIdx.x * blockDim.x + threadIdx.x;
    if (u < 32768) {
        float4 v = reinterpret_cast<const float4*>(W)[u];
        uint2 ph;
        ph.x = ((uint32_t)__half_as_ushort(__float2half_rn(v.y)) << 16) |
               __half_as_ushort(__float2half_rn(v.x));
        ph.y = ((uint32_t)__half_as_ushort(__float2half_rn(v.w)) << 16) |
               __half_as_ushort(__float2half_rn(v.z));
        reinterpret_cast<uint2*>(g_wh)[u] = ph;
    }
}

// ---------------------------------------------------------------------------
// Kernel 1: x_proj = x @ W_ih^T + bias, fp16 wmma m16n16k16, fp32 accum/out.
// BM=128 BN=256 BK=64, warp tile 64x64, 2-stage cp.async (v2-validated flow).
// smem (halves): Asm[2][128*72] | Wsm[2][256*72] | BiasT float[16*260]
// ---------------------------------------------------------------------------
#define HP 72                    // fp16 smem pitch (halves)
#define A_ST (128 * HP)          // 9216 halves per A stage
#define W_ST (256 * HP)          // 18432 halves per W stage
#define GEMM_SMEM ((2 * A_ST + 2 * W_ST) * 2 + 16 * 260 * 4)   // 127232 B

__global__ __launch_bounds__(256, 1)
void xproj_gemm_h(const float* __restrict__ bih, const float* __restrict__ bhh)
{
    extern __shared__ __half hsm[];
    __half* Asm = hsm;
    __half* Wsm = hsm + 2 * A_ST;
    float* BiasT = reinterpret_cast<float*>(hsm + 2 * A_ST + 2 * W_ST);

    const int n0  = blockIdx.x * 256;
    const int m0  = blockIdx.y * 128;
    const int tid = threadIdx.x;
    const int warp = tid >> 5;
    const int wm = (warp >> 2) * 64;
    const int wn = (warp & 3) * 64;

    const uint32_t a_b = smem_u32(Asm);
    const uint32_t w_b = smem_u32(Wsm);

    for (int i = tid; i < 16 * 256; i += 256) {
        int r = i >> 8, c = i & 255;
        BiasT[r * 260 + c] = bih[n0 + c] + bhh[n0 + c];
    }
    __syncthreads();

    wmma::fragment<wmma::accumulator, 16, 16, 16, float> cf[4][4];
#pragma unroll
    for (int i = 0; i < 4; i++)
#pragma unroll
        for (int j = 0; j < 4; j++)
            wmma::load_matrix_sync(cf[i][j], &BiasT[wn + j * 16], 260, wmma::mem_row_major);
    __syncthreads();

    // chunk issue: A 128x64 halves (1024 cp16), W 256x64 halves (2048 cp16)
    auto issue = [&](int kt, int s) {
#pragma unroll
        for (int it = 0; it < 4; it++) {
            int u = tid + it * 256;
            int row = u >> 3, ko = (u & 7) * 8;
            cp16(a_b + (uint32_t)(s * A_ST + row * HP + ko) * 2,
                 &g_xh16[(size_t)(m0 + row) * 256 + kt * 64 + ko]);
        }
#pragma unroll
        for (int it = 0; it < 8; it++) {
            int u = tid + it * 256;
            int row = u >> 3, ko = (u & 7) * 8;
            cp16(w_b + (uint32_t)(s * W_ST + row * HP + ko) * 2,
                 &g_wh[(size_t)(n0 + row) * 256 + kt * 64 + ko]);
        }
        cp_commit();
    };

    issue(0, 0);
    for (int kt = 0; kt < 4; kt++) {
        const int s = kt & 1;
        if (kt < 3) { issue(kt + 1, s ^ 1); cp_wait1(); }
        else        { cp_wait0(); }
        __syncthreads();
        const __half* As = Asm + s * A_ST;
        const __half* Ws = Wsm + s * W_ST;
#pragma unroll
        for (int kk = 0; kk < 64; kk += 16) {
            wmma::fragment<wmma::matrix_a, 16, 16, 16, __half, wmma::row_major> af[4];
            wmma::fragment<wmma::matrix_b, 16, 16, 16, __half, wmma::col_major> bf[4];
#pragma unroll
            for (int i = 0; i < 4; i++)
                wmma::load_matrix_sync(af[i], &As[(wm + i * 16) * HP + kk], HP);
#pragma unroll
            for (int j = 0; j < 4; j++)
                wmma::load_matrix_sync(bf[j], &Ws[(wn + j * 16) * HP + kk], HP);
#pragma unroll
            for (int i = 0; i < 4; i++)
#pragma unroll
                for (int j = 0; j < 4; j++)
                    wmma::mma_sync(cf[i][j], af[i], bf[j], cf[i][j]);
        }
        __syncthreads();
    }
#pragma unroll
    for (int i = 0; i < 4; i++)
#pragma unroll
        for (int j = 0; j < 4; j++)
            wmma::store_matrix_sync(
                &g_xproj[(size_t)(m0 + wm + i * 16) * 512 + n0 + wn + j * 16],
                cf[i][j], 512, wmma::mem_row_major);
}

// ---------------------------------------------------------------------------
// Recurrence: R12 lstm_rec_h6 VERBATIM (validated, 896us).
// ---------------------------------------------------------------------------
__device__ __forceinline__ void bt_write(char* bt, int e, int col, unsigned short v) {
    int kt = e >> 4, kk = e & 15;
    int half = kk >> 3, tq = (kk & 7) >> 1, lo2 = kk & 1;
    *reinterpret_cast<unsigned short*>(bt + kt * 256 + (col * 4 + tq) * 8 + half * 4 + lo2 * 2) = v;
}

__global__ __launch_bounds__(256, 1)
void lstm_rec_h6(const float* __restrict__ Whh,
                 const float* __restrict__ h0,
                 const float* __restrict__ c0,
                 float* __restrict__ out)
{
    __shared__ __align__(16) char  Btile[2][2048];
    __shared__ __align__(16) float xring[4][2048];

    const int tid = threadIdx.x;
    const int w   = tid >> 5;
    const int l   = tid & 31;
    const int bg0 = blockIdx.x * 4;
    const int j   = l & 3;
    const int p   = j & 1;
    const int cb  = (j < 2) ? 0 : 2;
    const int e   = w * 16 + (l >> 2) + ((j < 2) ? 0 : 8);

    uint32_t wf[4][8][4];
    {
        const int r0b = w * 16 + (l >> 2);
        const int t2  = 2 * (l & 3);
#pragma unroll
        for (int mt = 0; mt < 4; mt++)
#pragma unroll
            for (int kt = 0; kt < 8; kt++) {
                int r0 = mt * 128 + r0b;
                int k0 = kt * 16 + t2;
                const float* p00 = &Whh[(size_t)r0 * 128 + k0];
                const float* p10 = &Whh[(size_t)(r0 + 8) * 128 + k0];
                wf[mt][kt][0] = pkhf(p00[0], p00[1]);
                wf[mt][kt][1] = pkhf(p10[0], p10[1]);
                wf[mt][kt][2] = pkhf(p00[8], p00[9]);
                wf[mt][kt][3] = pkhf(p10[8], p10[9]);
            }
    }

    float creg[2];
#pragma unroll
    for (int i = 0; i < 2; i++) {
        int b = 2 * p + i;
        float h = h0[(size_t)(bg0 + b) * 128 + e];
        creg[i] = c0[(size_t)(bg0 + b) * 128 + e];
        __half hh = __float2half_rn(h);
        __half hl = __float2half_rn(h - __half2float(hh));
        bt_write(Btile[0], e, b,     __half_as_ushort(hh));
        bt_write(Btile[0], e, b + 4, __half_as_ushort(hl));
    }

    const uint32_t xr_b = smem_u32(xring);
    auto xissue = [&](int t) {
        if (t < T_STEPS) {
            const float* src = &g_xproj[((size_t)t * BATCH + bg0 + (tid >> 6)) * 512
                                        + (tid & 63) * 8];
            uint32_t dst = xr_b + (uint32_t)((t & 3) * 8192 + tid * 32);
            cp16(dst, src);
            cp16(dst + 16, src + 4);
        }
        cp_commit();
    };
    xissue(0); xissue(1); xissue(2);
    cp_wait2();
    float hprev[2] = {0.f, 0.f};
    __syncthreads();

    for (int t = 0; t < T_STEPS; t++) {
        const char* bt_rd = Btile[t & 1];
        char* bt_wr = Btile[(t + 1) & 1];

        if (t > 0) {
#pragma unroll
            for (int i = 0; i < 2; i++) {
                int b = 2 * p + i;
                out[((size_t)(t - 1) * BATCH + bg0 + b) * E_DIM + e] =
                    __logf(1.f + __expf(hprev[i]));
            }
        }

        float accA[4][4], accB[4][4];
#pragma unroll
        for (int mt = 0; mt < 4; mt++)
#pragma unroll
            for (int c = 0; c < 4; c++) { accA[mt][c] = 0.f; accB[mt][c] = 0.f; }
#pragma unroll
        for (int kt = 0; kt < 8; kt++) {
            uint2 bv = *reinterpret_cast<const uint2*>(bt_rd + kt * 256 + l * 8);
#pragma unroll
            for (int mt = 0; mt < 4; mt++)
                mma16816h((kt < 4) ? accA[mt] : accB[mt], wf[mt][kt], bv.x, bv.y);
        }

        float acc[4][4];
#pragma unroll
        for (int mt = 0; mt < 4; mt++)
#pragma unroll
            for (int c = 0; c < 4; c++) {
                float v = accA[mt][c] + accB[mt][c];
                acc[mt][c] = v + __shfl_xor_sync(0xffffffffu, v, 2);
            }

        const float* xs = xring[t & 3];
#pragma unroll
        for (int i = 0; i < 2; i++) {
            int c = cb + i;
            int b = 2 * p + i;
            const float* xrow = xs + b * 512 + e;
            float gi = acc[0][c] + xrow[0];
            float gf = acc[1][c] + xrow[128];
            float gg = acc[2][c] + xrow[256];
            float go = acc[3][c] + xrow[384];
            float i_ = sigma_(gi), f_ = sigma_(gf), o_ = sigma_(go);
            float g_ = tanha(gg);
            creg[i] = f_ * creg[i] + i_ * g_;
            float h = o_ * tanha(creg[i]);
            __half hh = __float2half_rn(h);
            __half hl = __float2half_rn(h - __half2float(hh));
            bt_write(bt_wr, e, b,     __half_as_ushort(hh));
            bt_write(bt_wr, e, b + 4, __half_as_ushort(hl));
            hprev[i] = h;
        }

        xissue(t + 3);
        cp_wait2();
        __syncthreads();
    }

#pragma unroll
    for (int i = 0; i < 2; i++) {
        int b = 2 * p + i;
        out[((size_t)(T_STEPS - 1) * BATCH + bg0 + b) * E_DIM + e] =
            __logf(1.f + __expf(hprev[i]));
    }
}

// ---------------------------------------------------------------------------
extern "C" void kernel_launch(void* const* d_in, const int* in_sizes, int n_in,
                              void* d_out, int out_size)
{
    const float* x   = (const float*)d_in[0];
    const float* h0  = (const float*)d_in[1];
    const float* c0  = (const float*)d_in[2];
    const float* Wih = (const float*)d_in[3];
    const float* Whh = (const float*)d_in[4];
    const float* bih = (const float*)d_in[5];
    const float* bhh = (const float*)d_in[6];
    float* out = (float*)d_out;

    cudaFuncSetAttribute((const void*)xproj_gemm_h,
                         cudaFuncAttributeMaxDynamicSharedMemorySize, GEMM_SMEM);

    prep_x16<<<2048, 256>>>(x);
    prep_w<<<128, 256>>>(Wih);
    xproj_gemm_h<<<dim3(2, 2048), 256, GEMM_SMEM>>>(bih, bhh);
    lstm_rec_h6<<<64, 256>>>(Whh, h0, c0, out);
}

// round 16
// speedup vs baseline: 2.2677x; 1.1223x over previous
#include <cuda_runtime.h>
#include <cuda_fp16.h>
#include <mma.h>
#include <math.h>
#include <stdint.h>

using namespace nvcuda;

#define T_STEPS 1024
#define BATCH   256
#define E_DIM   128

__device__ float  g_xproj[134217728];   // x_proj fp32 [M][512]
__device__ __half g_xh16[67108864];     // x fp16 [M=262144][256]
__device__ __half g_wh[131072];         // W_ih fp16 [512][256]

// ---------------------------------------------------------------------------
// helpers
// ---------------------------------------------------------------------------
__device__ __forceinline__ uint32_t smem_u32(const void* p) {
    uint32_t a;
    asm("{ .reg .u64 t; cvta.to.shared.u64 t, %1; cvt.u32.u64 %0, t; }" : "=r"(a) : "l"(p));
    return a;
}
__device__ __forceinline__ void cp16(uint32_t dst, const void* src) {
    asm volatile("cp.async.cg.shared.global [%0], [%1], 16;" :: "r"(dst), "l"(src));
}
__device__ __forceinline__ void cp_commit() { asm volatile("cp.async.commit_group;"); }
__device__ __forceinline__ void cp_wait0()  { asm volatile("cp.async.wait_group 0;"); }
__device__ __forceinline__ void cp_wait1()  { asm volatile("cp.async.wait_group 1;"); }
__device__ __forceinline__ void cp_wait2()  { asm volatile("cp.async.wait_group 2;"); }
__device__ __forceinline__ void mma16816h(float* c, const uint32_t* a, uint32_t b0, uint32_t b1) {
    asm volatile(
        "mma.sync.aligned.m16n8k16.row.col.f32.f16.f16.f32 "
        "{%0,%1,%2,%3}, {%4,%5,%6,%7}, {%8,%9}, {%0,%1,%2,%3};"
        : "+f"(c[0]), "+f"(c[1]), "+f"(c[2]), "+f"(c[3])
        : "r"(a[0]), "r"(a[1]), "r"(a[2]), "r"(a[3]), "r"(b0), "r"(b1));
}
__device__ __forceinline__ uint32_t pkhf(float x, float y) {
    __half2 h = __floats2half2_rn(x, y);
    return *reinterpret_cast<uint32_t*>(&h);
}
__device__ __forceinline__ float tanha(float x) {
    float r;
    asm("tanh.approx.f32 %0, %1;" : "=f"(r) : "f"(x));
    return r;
}
__device__ __forceinline__ float sigma_(float x) {
    return fmaf(0.5f, tanha(0.5f * x), 0.5f);
}

// ---------------------------------------------------------------------------
// Prep: x -> fp16, W_ih -> fp16 (validated R15)
// ---------------------------------------------------------------------------
__global__ void prep_x16(const float* __restrict__ x) {
    const int stride = gridDim.x * blockDim.x;
    for (int u = blockIdx.x * blockDim.x + threadIdx.x; u < 16777216; u += stride) {
        float4 v = reinterpret_cast<const float4*>(x)[u];
        uint2 ph;
        ph.x = ((uint32_t)__half_as_ushort(__float2half_rn(v.y)) << 16) |
               __half_as_ushort(__float2half_rn(v.x));
        ph.y = ((uint32_t)__half_as_ushort(__float2half_rn(v.w)) << 16) |
               __half_as_ushort(__float2half_rn(v.z));
        reinterpret_cast<uint2*>(g_xh16)[u] = ph;
    }
}
__global__ void prep_w(const float* __restrict__ W) {
    int u = blockIdx.x * blockDim.x + threadIdx.x;
    if (u < 32768) {
        float4 v = reinterpret_cast<const float4*>(W)[u];
        uint2 ph;
        ph.x = ((uint32_t)__half_as_ushort(__float2half_rn(v.y)) << 16) |
               __half_as_ushort(__float2half_rn(v.x));
        ph.y = ((uint32_t)__half_as_ushort(__float2half_rn(v.w)) << 16) |
               __half_as_ushort(__float2half_rn(v.z));
        reinterpret_cast<uint2*>(g_wh)[u] = ph;
    }
}

// ---------------------------------------------------------------------------
// Kernel 1: x_proj GEMM fp16 wmma (validated R15, ~280us). Unchanged.
// ---------------------------------------------------------------------------
#define HP 72
#define A_ST (128 * HP)
#define W_ST (256 * HP)
#define GEMM_SMEM ((2 * A_ST + 2 * W_ST) * 2 + 16 * 260 * 4)

__global__ __launch_bounds__(256, 1)
void xproj_gemm_h(const float* __restrict__ bih, const float* __restrict__ bhh)
{
    extern __shared__ __half hsm[];
    __half* Asm = hsm;
    __half* Wsm = hsm + 2 * A_ST;
    float* BiasT = reinterpret_cast<float*>(hsm + 2 * A_ST + 2 * W_ST);

    const int n0  = blockIdx.x * 256;
    const int m0  = blockIdx.y * 128;
    const int tid = threadIdx.x;
    const int warp = tid >> 5;
    const int wm = (warp >> 2) * 64;
    const int wn = (warp & 3) * 64;

    const uint32_t a_b = smem_u32(Asm);
    const uint32_t w_b = smem_u32(Wsm);

    for (int i = tid; i < 16 * 256; i += 256) {
        int r = i >> 8, c = i & 255;
        BiasT[r * 260 + c] = bih[n0 + c] + bhh[n0 + c];
    }
    __syncthreads();

    wmma::fragment<wmma::accumulator, 16, 16, 16, float> cf[4][4];
#pragma unroll
    for (int i = 0; i < 4; i++)
#pragma unroll
        for (int j = 0; j < 4; j++)
            wmma::load_matrix_sync(cf[i][j], &BiasT[wn + j * 16], 260, wmma::mem_row_major);
    __syncthreads();

    auto issue = [&](int kt, int s) {
#pragma unroll
        for (int it = 0; it < 4; it++) {
            int u = tid + it * 256;
            int row = u >> 3, ko = (u & 7) * 8;
            cp16(a_b + (uint32_t)(s * A_ST + row * HP + ko) * 2,
                 &g_xh16[(size_t)(m0 + row) * 256 + kt * 64 + ko]);
        }
#pragma unroll
        for (int it = 0; it < 8; it++) {
            int u = tid + it * 256;
            int row = u >> 3, ko = (u & 7) * 8;
            cp16(w_b + (uint32_t)(s * W_ST + row * HP + ko) * 2,
                 &g_wh[(size_t)(n0 + row) * 256 + kt * 64 + ko]);
        }
        cp_commit();
    };

    issue(0, 0);
    for (int kt = 0; kt < 4; kt++) {
        const int s = kt & 1;
        if (kt < 3) { issue(kt + 1, s ^ 1); cp_wait1(); }
        else        { cp_wait0(); }
        __syncthreads();
        const __half* As = Asm + s * A_ST;
        const __half* Ws = Wsm + s * W_ST;
#pragma unroll
        for (int kk = 0; kk < 64; kk += 16) {
            wmma::fragment<wmma::matrix_a, 16, 16, 16, __half, wmma::row_major> af[4];
            wmma::fragment<wmma::matrix_b, 16, 16, 16, __half, wmma::col_major> bf[4];
#pragma unroll
            for (int i = 0; i < 4; i++)
                wmma::load_matrix_sync(af[i], &As[(wm + i * 16) * HP + kk], HP);
#pragma unroll
            for (int j = 0; j < 4; j++)
                wmma::load_matrix_sync(bf[j], &Ws[(wn + j * 16) * HP + kk], HP);
#pragma unroll
            for (int i = 0; i < 4; i++)
#pragma unroll
                for (int j = 0; j < 4; j++)
                    wmma::mma_sync(cf[i][j], af[i], bf[j], cf[i][j]);
        }
        __syncthreads();
    }
#pragma unroll
    for (int i = 0; i < 4; i++)
#pragma unroll
        for (int j = 0; j < 4; j++)
            wmma::store_matrix_sync(
                &g_xproj[(size_t)(m0 + wm + i * 16) * 512 + n0 + wn + j * 16],
                cf[i][j], 512, wmma::mem_row_major);
}

// ---------------------------------------------------------------------------
// Recurrence: 16-warp m-split. 64 CTAs x 4 batches, 512 threads.
// Warp (q = w&3, mh = w>>2) owns gate rows q*128 + mh*32 (+0..31):
// 2 m16-tiles x 8 kt = 16 HMMA/warp. Gates redistributed via 8KB smem
// (conflict-free), epilogue 1 item/thread. B tile double-buffered,
// fp32 xring (cp.async 3 deep), deferred softplus. 2 bars/step.
// ---------------------------------------------------------------------------
__device__ __forceinline__ void bt_write(char* bt, int e, int col, unsigned short v) {
    int kt = e >> 4, kk = e & 15;
    int half = kk >> 3, tq = (kk & 7) >> 1, lo2 = kk & 1;
    *reinterpret_cast<unsigned short*>(bt + kt * 256 + (col * 4 + tq) * 8 + half * 4 + lo2 * 2) = v;
}

__global__ __launch_bounds__(512, 1)
void lstm_rec_m16(const float* __restrict__ Whh,
                  const float* __restrict__ h0,
                  const float* __restrict__ c0,
                  float* __restrict__ out)
{
    __shared__ __align__(16) char  Btile[2][2048];
    __shared__ __align__(16) float gsm[2048];        // [512 rows][4 batches]
    __shared__ __align__(16) float xring[4][2048];   // 32 KB

    const int tid = threadIdx.x;
    const int w   = tid >> 5;
    const int l   = tid & 31;
    const int q   = w & 3;           // gate type
    const int mh  = w >> 2;          // row-group within gate
    const int bg0 = blockIdx.x * 4;
    const int g0  = q * 128 + mh * 32;

    // ---- W_hh fp16 A-fragments: 2 m16-tiles x 8 kt ----
    uint32_t wf[2][8][4];
    {
        const int t2 = 2 * (l & 3);
#pragma unroll
        for (int ti = 0; ti < 2; ti++)
#pragma unroll
            for (int kt = 0; kt < 8; kt++) {
                int r0 = g0 + ti * 16 + (l >> 2);
                int k0 = kt * 16 + t2;
                const float* p00 = &Whh[(size_t)r0 * 128 + k0];
                const float* p10 = &Whh[(size_t)(r0 + 8) * 128 + k0];
                wf[ti][kt][0] = pkhf(p00[0], p00[1]);
                wf[ti][kt][1] = pkhf(p10[0], p10[1]);
                wf[ti][kt][2] = pkhf(p00[8], p00[9]);
                wf[ti][kt][3] = pkhf(p10[8], p10[9]);
            }
    }

    // ---- state: 1 item (e, b) per thread ----
    const int e = tid >> 2;
    const int b = tid & 3;
    float creg = c0[(size_t)(bg0 + b) * 128 + e];
    {
        float h = h0[(size_t)(bg0 + b) * 128 + e];
        __half hh = __float2half_rn(h);
        __half hl = __float2half_rn(h - __half2float(hh));
        bt_write(Btile[0], e, b,     __half_as_ushort(hh));
        bt_write(Btile[0], e, b + 4, __half_as_ushort(hl));
    }

    // ---- xring: thread copies 4 floats/stage ----
    const uint32_t xr_b = smem_u32(xring);
    auto xissue = [&](int t) {
        if (t < T_STEPS)
            cp16(xr_b + (uint32_t)((t & 3) * 8192 + tid * 16),
                 &g_xproj[((size_t)t * BATCH + bg0 + (tid >> 7)) * 512 + (tid & 127) * 4]);
        cp_commit();
    };
    xissue(0); xissue(1); xissue(2);
    cp_wait2();
    float hprev = 0.f;
    __syncthreads();

    const bool writer = (l & 3) < 2;   // lanes holding unique gate values

    for (int t = 0; t < T_STEPS; t++) {
        const char* bt_rd = Btile[t & 1];
        char* bt_wr = Btile[(t + 1) & 1];

        // deferred softplus + STG for t-1 (overlaps MMA)
        if (t > 0)
            out[((size_t)(t - 1) * BATCH + bg0 + b) * E_DIM + e] =
                __logf(1.f + __expf(hprev));

        // ---- MMA sweep: 16 HMMA, 4 independent chains ----
        float accA[2][4], accB[2][4];
#pragma unroll
        for (int ti = 0; ti < 2; ti++)
#pragma unroll
            for (int c = 0; c < 4; c++) { accA[ti][c] = 0.f; accB[ti][c] = 0.f; }
#pragma unroll
        for (int kt = 0; kt < 8; kt++) {
            uint2 bv = *reinterpret_cast<const uint2*>(bt_rd + kt * 256 + l * 8);
#pragma unroll
            for (int ti = 0; ti < 2; ti++)
                mma16816h((kt < 4) ? accA[ti] : accB[ti], wf[ti][kt], bv.x, bv.y);
        }

        // ---- hi/lo butterfly + gate STS ----
#pragma unroll
        for (int ti = 0; ti < 2; ti++)
#pragma unroll
            for (int c = 0; c < 4; c++) {
                float v = accA[ti][c] + accB[ti][c];
                v += __shfl_xor_sync(0xffffffffu, v, 2);
                if (writer) {
                    int row = g0 + ti * 16 + (l >> 2) + 8 * (c >> 1);
                    int bb  = 2 * (l & 3) + (c & 1);
                    gsm[row * 4 + bb] = v;
                }
            }
        __syncthreads();   // bar1: gates visible (also: all MMA reads of bt_rd done)

        // ---- epilogue: 1 item/thread; gate q at gsm[q*512 + tid] ----
        {
            const float* xrow = xring[t & 3] + b * 512 + e;
            float gi = gsm[0 * 512 + tid] + xrow[0];
            float gf = gsm[1 * 512 + tid] + xrow[128];
            float gg = gsm[2 * 512 + tid] + xrow[256];
            float go = gsm[3 * 512 + tid] + xrow[384];
            float i_ = sigma_(gi), f_ = sigma_(gf), o_ = sigma_(go);
            float g_ = tanha(gg);
            creg = f_ * creg + i_ * g_;
            float h = o_ * tanha(creg);
            __half hh = __float2half_rn(h);
            __half hl = __float2half_rn(h - __half2float(hh));
            bt_write(bt_wr, e, b,     __half_as_ushort(hh));
            bt_write(bt_wr, e, b + 4, __half_as_ushort(hl));
            hprev = h;
        }

        xissue(t + 3);
        cp_wait2();
        __syncthreads();   // bar2: bt_wr + ring stage visible; gsm safe to rewrite
    }

    out[((size_t)(T_STEPS - 1) * BATCH + bg0 + b) * E_DIM + e] =
        __logf(1.f + __expf(hprev));
}

// ---------------------------------------------------------------------------
extern "C" void kernel_launch(void* const* d_in, const int* in_sizes, int n_in,
                              void* d_out, int out_size)
{
    const float* x   = (const float*)d_in[0];
    const float* h0  = (const float*)d_in[1];
    const float* c0  = (const float*)d_in[2];
    const float* Wih = (const float*)d_in[3];
    const float* Whh = (const float*)d_in[4];
    const float* bih = (const float*)d_in[5];
    const float* bhh = (const float*)d_in[6];
    float* out = (float*)d_out;

    cudaFuncSetAttribute((const void*)xproj_gemm_h,
                         cudaFuncAttributeMaxDynamicSharedMemorySize, GEMM_SMEM);

    prep_x16<<<2048, 256>>>(x);
    prep_w<<<128, 256>>>(Wih);
    xproj_gemm_h<<<dim3(2, 2048), 256, GEMM_SMEM>>>(bih, bhh);
    lstm_rec_m16<<<64, 512>>>(Whh, h0, c0, out);
}